// round 16
// baseline (speedup 1.0000x reference)
#include <cuda_runtime.h>
#include <cuda_bf16.h>
#include <cstdint>

#define FULLMASK 0xffffffffu
#define MAXL 32
#define PIPE 4          // cp.async row buffers per warp (8 KB)
#define HOTK 64         // node id < HOTK => hot top-of-tree row (L1-cached LDG)

typedef unsigned int       u32;
typedef unsigned long long u64;

// HierarchicalSoftmax. One warp per sample. Key data property (provable from
// the heapq Huffman build): node ids along each path are STRICTLY DECREASING
// (deepest merge first, root id 0 last). So each path = deep prefix (large ids,
// read-once) + hot suffix (ids < HOTK, shared by every warp).
//   deep prefix  -> cp.async.cg ring (bypasses both the L1 fill AND the
//                   ~248-entry per-SM L1tex LDG queue; unbounded depth)
//   hot suffix   -> plain LDG, hitting an unthrashed L1 (128 KB hot set)
// Butterfly transposes per-step sums onto lanes as in prior rounds.
// Validity: active[l] = (l<L) && (l==0 || node[l-1]!=0); masks are prefixes.

__device__ __forceinline__ u64 ffma2(u64 a, u64 b, u64 c)
{
    u64 d;
    asm("fma.rn.f32x2 %0, %1, %2, %3;" : "=l"(d) : "l"(a), "l"(b), "l"(c));
    return d;
}

__device__ __forceinline__ float f32x2_hsum(u64 p)
{
    float lo, hi;
    asm("mov.b64 {%0, %1}, %2;" : "=f"(lo), "=f"(hi) : "l"(p));
    return lo + hi;
}

__device__ __forceinline__ u32 smem_u32(const void* p)
{
    u32 a;
    asm("{ .reg .u64 t; cvta.to.shared.u64 t, %1; cvt.u32.u64 %0, t; }"
        : "=r"(a) : "l"(p));
    return a;
}

__device__ __forceinline__ void cp16(u32 dst, const void* src)
{
    asm volatile("cp.async.cg.shared.global [%0], [%1], 16;"
                 :: "r"(dst), "l"(src) : "memory");
}
#define CP_COMMIT() asm volatile("cp.async.commit_group;" ::: "memory")
#define CP_WAIT(n)  asm volatile("cp.async.wait_group %0;" :: "n"(n) : "memory")

__device__ __forceinline__ float dot_u2(ulonglong2 w0, ulonglong2 w1,
                                        ulonglong2 w2, ulonglong2 w3,
                                        ulonglong2 ea, ulonglong2 eb,
                                        ulonglong2 ec, ulonglong2 ed)
{
    u64 p = ffma2(ea.x, w0.x, 0ULL);
    p = ffma2(ea.y, w0.y, p);
    p = ffma2(eb.x, w1.x, p);
    p = ffma2(eb.y, w1.y, p);
    p = ffma2(ec.x, w2.x, p);
    p = ffma2(ec.y, w2.y, p);
    p = ffma2(ed.x, w3.x, p);
    p = ffma2(ed.y, w3.y, p);
    return f32x2_hsum(p);
}

__device__ __forceinline__ float butterfly16(float (&acc)[16], int lane)
{
    #pragma unroll
    for (int h = 8; h >= 1; h >>= 1) {
        #pragma unroll
        for (int i = 0; i < h; ++i) {
            float v = acc[i], w = acc[i + h];
            float give = (lane & h) ? v : w;
            float got  = __shfl_xor_sync(FULLMASK, give, h);
            acc[i] = ((lane & h) ? w : v) + got;
        }
    }
    return acc[0] + __shfl_xor_sync(FULLMASK, acc[0], 16);
}

__global__ __launch_bounds__(128, 6)
void hs512_v16_kernel(const float* __restrict__ emb,
                      const float* __restrict__ W,
                      const float* __restrict__ bias,
                      const int*   __restrict__ target,
                      const int*   __restrict__ path_nodes,
                      const int*   __restrict__ path_dirs,
                      float*       __restrict__ out,
                      int B, int L)
{
    __shared__ float4 sbuf[4][PIPE][128];          // 32 KB: 4 warps x 4 x 2KB rows

    const int D16 = 512 / 4;
    int wid  = threadIdx.x >> 5;
    int lane = threadIdx.x & 31;
    int gw   = (blockIdx.x * blockDim.x + threadIdx.x) >> 5;   // one warp/sample
    if (gw >= B) return;                           // no block-wide sync used

    int t = __ldg(target + gw);

    // Embedding: streaming loads (read-once; keep out of the hot L1 set).
    const ulonglong2* ev = reinterpret_cast<const ulonglong2*>(emb) + (size_t)gw * D16;
    ulonglong2 ea = __ldcs(ev + lane +  0);
    ulonglong2 eb = __ldcs(ev + lane + 32);
    ulonglong2 ec = __ldcs(ev + lane + 64);
    ulonglong2 ed = __ldcs(ev + lane + 96);

    const int* nrow = path_nodes + (size_t)t * L;
    const int* drow = path_dirs  + (size_t)t * L;
    int my_node = (lane < L) ? __ldg(nrow + lane) : 0;
    int my_dir  = (lane < L) ? __ldg(drow + lane) : 0;

    int prev = __shfl_up_sync(FULLMASK, my_node, 1);
    bool act = (lane < L) && (lane == 0 || prev != 0);
    unsigned am = __ballot_sync(FULLMASK, act);    // contiguous prefix mask
    int n = __popc(am);                            // path length

    // Deep steps = prefix of path with node id >= HOTK (ids strictly decrease).
    unsigned dm = __ballot_sync(FULLMASK, act && (my_node >= HOTK));
    int nd = __popc(dm);                           // deep-prefix length

    float my_bias = act ? __ldg(bias + my_node) : 0.0f;

    const char* Wb = reinterpret_cast<const char*>(W);
    const ulonglong2* Wv = reinterpret_cast<const ulonglong2*>(W);
    u32 sb = smem_u32(&sbuf[wid][0][0]);

    float accA[16], accB[16];
    #pragma unroll
    for (int i = 0; i < 16; ++i) { accA[i] = 0.0f; accB[i] = 0.0f; }
    #define ACCSET(idx, val) do { if ((idx) < 16) accA[(idx)] = (val); \
                                  else accB[(idx) - 16] = (val); } while (0)

    // ── cp.async prologue: fill PIPE-1 ring slots (always commit -> exact counts).
    #pragma unroll
    for (int i = 0; i < PIPE - 1; ++i) {
        if (i < nd) {
            int node = __shfl_sync(FULLMASK, my_node, i);
            const char* src = Wb + (size_t)node * 2048 + lane * 16;
            u32 dst = sb + (u32)(i & (PIPE - 1)) * 2048 + lane * 16;
            cp16(dst,        src       );
            cp16(dst +  512, src +  512);
            cp16(dst + 1024, src + 1024);
            cp16(dst + 1536, src + 1536);
        }
        CP_COMMIT();
    }

    // ── Hot suffix via LDG while the first deep rows are in flight.
    #pragma unroll
    for (int i = 0; i < MAXL; ++i) {
        if (i >= n) break;                          // uniform
        if (i >= nd) {                              // hot step (node < HOTK)
            int node = __shfl_sync(FULLMASK, my_node, i);
            const ulonglong2* w = Wv + (size_t)node * 128;
            ulonglong2 w0 = w[lane +  0];
            ulonglong2 w1 = w[lane + 32];
            ulonglong2 w2 = w[lane + 64];
            ulonglong2 w3 = w[lane + 96];
            float s = dot_u2(w0, w1, w2, w3, ea, eb, ec, ed);
            ACCSET(i, s);
        }
    }

    // ── Deep prefix: cp.async ring, one group per iteration (empty ok).
    #pragma unroll
    for (int i = 0; i < MAXL; ++i) {
        if (i >= nd) break;                         // uniform
        int j = i + PIPE - 1;
        if (j < nd) {
            int node = __shfl_sync(FULLMASK, my_node, j);
            const char* src = Wb + (size_t)node * 2048 + lane * 16;
            u32 dst = sb + (u32)(j & (PIPE - 1)) * 2048 + lane * 16;
            cp16(dst,        src       );
            cp16(dst +  512, src +  512);
            cp16(dst + 1024, src + 1024);
            cp16(dst + 1536, src + 1536);
        }
        CP_COMMIT();
        CP_WAIT(PIPE - 1);                          // row i's group retired
        const ulonglong2* w =
            reinterpret_cast<const ulonglong2*>(&sbuf[wid][i & (PIPE - 1)][0]);
        ulonglong2 w0 = w[lane +  0];
        ulonglong2 w1 = w[lane + 32];
        ulonglong2 w2 = w[lane + 64];
        ulonglong2 w3 = w[lane + 96];
        float s = dot_u2(w0, w1, w2, w3, ea, eb, ec, ed);
        ACCSET(i, s);
    }

    // ── Butterflies: lane l ends with step l's full dot product.
    float sA = butterfly16(accA, lane);
    float sB = 0.0f;
    if (am >> 16)
        sB = butterfly16(accB, lane);

    float dotv = (lane < 16) ? sA : sB;
    float f = 1.0f;
    if (act) {
        float sc = dotv + my_bias;
        float sg = my_dir ? sc : -sc;
        f = __fdividef(1.0f, 1.0f + __expf(-sg));
    }
    #pragma unroll
    for (int o = 16; o >= 1; o >>= 1)
        f *= __shfl_xor_sync(FULLMASK, f, o);

    if (lane == 0) out[gw] = f;
    #undef ACCSET
}

// Generic fallback (any D, any L) — shape safety, not the hot path.
__global__ __launch_bounds__(256)
void hs_generic_kernel(const float* __restrict__ emb,
                       const float* __restrict__ W,
                       const float* __restrict__ bias,
                       const int*   __restrict__ target,
                       const int*   __restrict__ path_nodes,
                       const int*   __restrict__ path_dirs,
                       float*       __restrict__ out,
                       int B, int D, int L)
{
    int gw   = (blockIdx.x * blockDim.x + threadIdx.x) >> 5;
    int lane = threadIdx.x & 31;
    if (gw >= B) return;

    const float* e = emb + (size_t)gw * D;
    int t = __ldg(target + gw);
    const int* nrow = path_nodes + (size_t)t * L;
    const int* drow = path_dirs  + (size_t)t * L;

    float prod = 1.0f;
    for (int l = 0; l < L; ++l) {
        int node = __ldg(nrow + l);
        int dir  = __ldg(drow + l);
        const float* w = W + (size_t)node * D;
        float acc = 0.0f;
        for (int d = lane; d < D; d += 32)
            acc = fmaf(e[d], w[d], acc);
        #pragma unroll
        for (int off = 16; off > 0; off >>= 1)
            acc += __shfl_xor_sync(FULLMASK, acc, off);
        float s  = acc + __ldg(bias + node);
        float sg = dir ? s : -s;
        prod *= __fdividef(1.0f, 1.0f + __expf(-sg));
        if (node == 0) break;
    }
    if (lane == 0) out[gw] = prod;
}

extern "C" void kernel_launch(void* const* d_in, const int* in_sizes, int n_in,
                              void* d_out, int out_size)
{
    const float* emb    = (const float*)d_in[0];   // [B, D] f32
    const float* W      = (const float*)d_in[1];   // [V-1, D] f32
    const float* bias   = (const float*)d_in[2];   // [V-1] f32
    const int*   target = (const int*)  d_in[3];   // [B] i32
    const int*   nodes  = (const int*)  d_in[4];   // [V, L] i32
    const int*   dirs   = (const int*)  d_in[5];   // [V, L] i32
    // d_in[6] = path_mask: unused (validity derived from node==0 sentinel)

    int B = in_sizes[3];
    int D = in_sizes[0] / B;
    int V = in_sizes[2] + 1;
    int L = in_sizes[4] / V;
    float* out = (float*)d_out;

    if (D == 512 && L <= MAXL && V - 1 >= HOTK) {
        // Favor shared memory so 6 blocks x 32 KB ring buffers co-reside.
        cudaFuncSetAttribute(hs512_v16_kernel,
                             cudaFuncAttributePreferredSharedMemoryCarveout,
                             cudaSharedmemCarveoutMaxShared);
        int threads = 128;                         // 4 warps = 4 samples per block
        int blocks  = (B * 32 + threads - 1) / threads;
        hs512_v16_kernel<<<blocks, threads>>>(emb, W, bias, target, nodes, dirs, out, B, L);
    } else {
        int threads = 256;
        int blocks  = (B * 32 + threads - 1) / threads;
        hs_generic_kernel<<<blocks, threads>>>(emb, W, bias, target, nodes, dirs, out, B, D, L);
    }
}

// round 17
// speedup vs baseline: 1.2548x; 1.2548x over previous
#include <cuda_runtime.h>
#include <cuda_bf16.h>
#include <cstdint>

#define FULLMASK 0xffffffffu
#define MAXL 32

// HierarchicalSoftmax. One warp per sample; two 16-step chunks, each a batched
// W-row load burst + 16-acc register butterfly that transposes step-sums onto
// lanes (lane l ends with the dot product of step l).
//
// v17: all bulk loads use Blackwell 256-bit vector loads (ld.global.nc.v8.f32
// -> LDG.E.256): identical bytes/sectors but HALF the L1tex queue entries and
// LSU issue ops per W row (2 per lane instead of 4). Tests whether the per-SM
// load queue is entry-limited. Scheduling/reduction identical to the 12.7us
// champion (v9/v13).
//
// Path validity from data: Huffman root id 0 is the LAST valid entry of every
// path; padding is also 0 -> active[l] = (l<L) && (l==0 || node[l-1]!=0).

struct f256 { float a0, a1, a2, a3, a4, a5, a6, a7; };

__device__ __forceinline__ f256 ldg256(const float* p)
{
    f256 r;
    asm("ld.global.nc.v8.f32 {%0,%1,%2,%3,%4,%5,%6,%7}, [%8];"
        : "=f"(r.a0), "=f"(r.a1), "=f"(r.a2), "=f"(r.a3),
          "=f"(r.a4), "=f"(r.a5), "=f"(r.a6), "=f"(r.a7)
        : "l"(p));
    return r;
}

__device__ __forceinline__ float dot8(const f256& e, const f256& w, float s)
{
    s = fmaf(e.a0, w.a0, s);
    s = fmaf(e.a1, w.a1, s);
    s = fmaf(e.a2, w.a2, s);
    s = fmaf(e.a3, w.a3, s);
    s = fmaf(e.a4, w.a4, s);
    s = fmaf(e.a5, w.a5, s);
    s = fmaf(e.a6, w.a6, s);
    s = fmaf(e.a7, w.a7, s);
    return s;
}

// Dot of 16 path steps. Each lane owns floats [lane*8, lane*8+8) and
// [1024/4 + lane*8, ...) of each 512-float row: 2x LDG.256, coalesced.
__device__ __forceinline__ float hs_dot16v(const float* __restrict__ W,
                                           unsigned am, int base, int my_node,
                                           int lane,
                                           const f256& e0, const f256& e1)
{
    float acc[16];
    #pragma unroll
    for (int i = 0; i < 16; ++i) {
        float s = 0.0f;
        if ((am >> (base + i)) & 1u) {               // warp-uniform (prefix mask)
            int node = __shfl_sync(FULLMASK, my_node, base + i);
            const float* w = W + (size_t)node * 512 + lane * 8;
            f256 w0 = ldg256(w);
            f256 w1 = ldg256(w + 256);
            s = dot8(e0, w0, s);
            s = dot8(e1, w1, s);
        }
        acc[i] = s;
    }
    // Butterfly: strides 8..1 reduce within each 16-lane half; afterwards lane l
    // holds the half-sum of step (l & 15). Stride-16 combine -> full dot product.
    #pragma unroll
    for (int h = 8; h >= 1; h >>= 1) {
        #pragma unroll
        for (int i = 0; i < h; ++i) {
            float v = acc[i], w = acc[i + h];
            float give = (lane & h) ? v : w;
            float got  = __shfl_xor_sync(FULLMASK, give, h);
            acc[i] = ((lane & h) ? w : v) + got;
        }
    }
    return acc[0] + __shfl_xor_sync(FULLMASK, acc[0], 16);
}

__global__ __launch_bounds__(128, 7)
void hs512_v17_kernel(const float* __restrict__ emb,
                      const float* __restrict__ W,
                      const float* __restrict__ bias,
                      const int*   __restrict__ target,
                      const int*   __restrict__ path_nodes,
                      const int*   __restrict__ path_dirs,
                      float*       __restrict__ out,
                      int B, int L)
{
    int gw   = (blockIdx.x * blockDim.x + threadIdx.x) >> 5;   // one warp per sample
    int lane = threadIdx.x & 31;
    if (gw >= B) return;

    int t = __ldg(target + gw);

    // Embedding row in registers: 2x LDG.256 per lane, coalesced.
    const float* e = emb + (size_t)gw * 512 + lane * 8;
    f256 e0 = ldg256(e);
    f256 e1 = ldg256(e + 256);

    const int* nrow = path_nodes + (size_t)t * L;
    const int* drow = path_dirs  + (size_t)t * L;

    // Coalesced per-lane node/dir loads: lane l owns path step l.
    int my_node = (lane < L) ? __ldg(nrow + lane) : 0;
    int my_dir  = (lane < L) ? __ldg(drow + lane) : 0;

    // Active mask via shfl_up + ballot (root id 0 terminates the path).
    int prev = __shfl_up_sync(FULLMASK, my_node, 1);
    bool act = (lane < L) && (lane == 0 || prev != 0);
    unsigned am = __ballot_sync(FULLMASK, act);

    // Bias prefetch: hidden under the W bursts.
    float my_bias = act ? __ldg(bias + my_node) : 0.0f;

    // Chunk A: steps 0..15. Lane l gets dot of step (l & 15).
    float sA = hs_dot16v(W, am, 0, my_node, lane, e0, e1);

    // Chunk B: steps 16..31 — warp-uniform skip when the path is short.
    float sB = 0.0f;
    if (am >> 16)
        sB = hs_dot16v(W, am, 16, my_node, lane, e0, e1);

    // Epilogue: lane l holds step l's dot (sA for l<16, sB for l>=16 since
    // base + (l & 15) == l). One sigmoid per active lane.
    float dotv = (lane < 16) ? sA : sB;
    float f = 1.0f;
    if (act) {
        float sc = dotv + my_bias;
        float sg = my_dir ? sc : -sc;
        f = __fdividef(1.0f, 1.0f + __expf(-sg));
    }
    #pragma unroll
    for (int o = 16; o >= 1; o >>= 1)
        f *= __shfl_xor_sync(FULLMASK, f, o);

    if (lane == 0) out[gw] = f;
}

// Generic fallback (any D, any L) — shape safety, not the hot path.
__global__ __launch_bounds__(256)
void hs_generic_kernel(const float* __restrict__ emb,
                       const float* __restrict__ W,
                       const float* __restrict__ bias,
                       const int*   __restrict__ target,
                       const int*   __restrict__ path_nodes,
                       const int*   __restrict__ path_dirs,
                       float*       __restrict__ out,
                       int B, int D, int L)
{
    int gw   = (blockIdx.x * blockDim.x + threadIdx.x) >> 5;
    int lane = threadIdx.x & 31;
    if (gw >= B) return;

    const float* e = emb + (size_t)gw * D;
    int t = __ldg(target + gw);
    const int* nrow = path_nodes + (size_t)t * L;
    const int* drow = path_dirs  + (size_t)t * L;

    float prod = 1.0f;
    for (int l = 0; l < L; ++l) {
        int node = __ldg(nrow + l);
        int dir  = __ldg(drow + l);
        const float* w = W + (size_t)node * D;
        float acc = 0.0f;
        for (int d = lane; d < D; d += 32)
            acc = fmaf(e[d], w[d], acc);
        #pragma unroll
        for (int off = 16; off > 0; off >>= 1)
            acc += __shfl_xor_sync(FULLMASK, acc, off);
        float s  = acc + __ldg(bias + node);
        float sg = dir ? s : -s;
        prod *= __fdividef(1.0f, 1.0f + __expf(-sg));
        if (node == 0) break;
    }
    if (lane == 0) out[gw] = prod;
}

extern "C" void kernel_launch(void* const* d_in, const int* in_sizes, int n_in,
                              void* d_out, int out_size)
{
    const float* emb    = (const float*)d_in[0];   // [B, D] f32
    const float* W      = (const float*)d_in[1];   // [V-1, D] f32
    const float* bias   = (const float*)d_in[2];   // [V-1] f32
    const int*   target = (const int*)  d_in[3];   // [B] i32
    const int*   nodes  = (const int*)  d_in[4];   // [V, L] i32
    const int*   dirs   = (const int*)  d_in[5];   // [V, L] i32
    // d_in[6] = path_mask: unused (validity derived from node==0 sentinel)

    int B = in_sizes[3];
    int D = in_sizes[0] / B;
    int V = in_sizes[2] + 1;
    int L = in_sizes[4] / V;
    float* out = (float*)d_out;

    if (D == 512 && L <= MAXL) {
        int threads = 128;                         // 4 warps = 4 samples per block
        int blocks  = (B * 32 + threads - 1) / threads;
        hs512_v17_kernel<<<blocks, threads>>>(emb, W, bias, target, nodes, dirs, out, B, L);
    } else {
        int threads = 256;
        int blocks  = (B * 32 + threads - 1) / threads;
        hs_generic_kernel<<<blocks, threads>>>(emb, W, bias, target, nodes, dirs, out, B, D, L);
    }
}